// round 5
// baseline (speedup 1.0000x reference)
#include <cuda_runtime.h>

// ---------------------------------------------------------------------------
// HierarchicalStageMoE — fp32 implementation with FFMA2 (f32x2) tiled GEMMs.
//
// Shapes: B*T = 8192 tokens, D=1024, F=64, DFE=128, RIN=1152, DRH=256,
//         NB=4, FPB=16, ES=4, NE=16, DEH=512.
// Outputs concatenated in d_out (float32), reference tuple order:
//   next_hidden[8192,1024], gate_weights[8192,16], gate_logits[8192,16],
//   bundle_weights[8192,4], bundle_logits[8192,4], stage_delta[8192,1024]
// ---------------------------------------------------------------------------

#define M_TOK 8192
#define D_HID 1024
#define F_FEAT 64
#define DFE 128
#define RIN 1152
#define DRH 256
#define NB 4
#define FPB 16
#define ES 4
#define NE 16
#define DEH 512
#define NEH (NE * DEH)  // 8192

#define OFF_NH 0
#define OFF_GW (M_TOK * D_HID)
#define OFF_GL (OFF_GW + M_TOK * NE)
#define OFF_BW (OFF_GL + M_TOK * NE)
#define OFF_BL (OFF_BW + M_TOK * NB)
#define OFF_SD (OFF_BL + M_TOK * NB)

typedef unsigned long long ull;

// ------------------------- scratch (static device memory) ------------------
__device__ float g_hnorm[M_TOK * D_HID];        // 32 MB
__device__ float g_sfe[M_TOK * DFE];            // 4 MB
__device__ float g_bemb[M_TOK * NB * DFE];      // 16 MB
__device__ float g_bh[M_TOK * DRH];             // 8 MB
__device__ float g_ih[M_TOK * NB * DRH];        // 32 MB
__device__ float g_gate[M_TOK * NE];            // 0.5 MB
__device__ float g_eh[(size_t)M_TOK * NEH];     // 268 MB (gate-scaled gelu(h@W1+b1))

// ------------------------- small helpers -----------------------------------
__device__ __forceinline__ float gelu_f(float x) {
    return 0.5f * x * (1.0f + erff(x * 0.70710678118654752440f));
}

__device__ __forceinline__ ull ffma2(ull a, ull b, ull c) {
    ull d;
    asm("fma.rn.f32x2 %0, %1, %2, %3;" : "=l"(d) : "l"(a), "l"(b), "l"(c));
    return d;
}
__device__ __forceinline__ ull pk2(float x, float y) {
    ull r;
    asm("mov.b64 %0, {%1, %2};" : "=l"(r) : "f"(x), "f"(y));
    return r;
}
__device__ __forceinline__ float2 upk2(ull v) {
    float2 r;
    asm("mov.b64 {%0, %1}, %2;" : "=f"(r.x), "=f"(r.y) : "l"(v));
    return r;
}

// ---------------------------------------------------------------------------
// Kernel 1: LayerNorm + stage feature embedding + per-bundle feature embedding
// ---------------------------------------------------------------------------
__global__ void __launch_bounds__(256) prep_kernel(
    const float* __restrict__ hidden, const float* __restrict__ feat,
    const float* __restrict__ ln_g, const float* __restrict__ ln_b,
    const float* __restrict__ stage_W, const float* __restrict__ stage_b,
    const float* __restrict__ bproj_W, const float* __restrict__ bproj_b)
{
    const int t = blockIdx.x;
    const int tid = threadIdx.x;
    __shared__ float red[256];
    __shared__ float sfeat[F_FEAT];

    const float* hrow = hidden + (size_t)t * D_HID;
    float x[4];
    float s = 0.f;
#pragma unroll
    for (int i = 0; i < 4; i++) { x[i] = hrow[tid + 256 * i]; s += x[i]; }
    if (tid < F_FEAT) sfeat[tid] = feat[(size_t)t * F_FEAT + tid];
    red[tid] = s;
    __syncthreads();
    for (int off = 128; off > 0; off >>= 1) {
        if (tid < off) red[tid] += red[tid + off];
        __syncthreads();
    }
    const float mu = red[0] * (1.0f / 1024.0f);
    __syncthreads();
    float v = 0.f;
#pragma unroll
    for (int i = 0; i < 4; i++) { float d = x[i] - mu; v += d * d; }
    red[tid] = v;
    __syncthreads();
    for (int off = 128; off > 0; off >>= 1) {
        if (tid < off) red[tid] += red[tid + off];
        __syncthreads();
    }
    const float rstd = rsqrtf(red[0] * (1.0f / 1024.0f) + 1e-5f);

#pragma unroll
    for (int i = 0; i < 4; i++) {
        int d = tid + 256 * i;
        g_hnorm[(size_t)t * D_HID + d] = (x[i] - mu) * rstd * ln_g[d] + ln_b[d];
    }
    // stage feature embedding: [64] @ [64,128] + b
    if (tid < DFE) {
        float acc = stage_b[tid];
#pragma unroll
        for (int f = 0; f < F_FEAT; f++) acc += sfeat[f] * stage_W[f * DFE + tid];
        g_sfe[(size_t)t * DFE + tid] = acc;
    }
    // bundle embeddings: per bundle g, [16] @ [16,128] + b
    for (int idx = tid; idx < NB * DFE; idx += 256) {
        int g = idx >> 7, j = idx & 127;
        float acc = bproj_b[g * DFE + j];
#pragma unroll
        for (int f = 0; f < FPB; f++)
            acc += sfeat[g * FPB + f] * bproj_W[(g * FPB + f) * DFE + j];
        g_bemb[(size_t)t * (NB * DFE) + idx] = acc;
    }
}

// ---------------------------------------------------------------------------
// Kernel 2/3: router GEMM1  (X = concat(h_norm, extra)) @ W1 + b1 -> gelu
// INTRA=0: bundle router (extra = g_sfe).  INTRA=1: z-th intra router.
// Tile 128x128x16, 256 threads, 8x8/thread via FFMA2.
// ---------------------------------------------------------------------------
template <int INTRA>
__global__ void __launch_bounds__(256) router_gemm(
    const float* __restrict__ W1, const float* __restrict__ b1)
{
    __shared__ float As[16][132];
    __shared__ float Bs[16][128];
    const int tid = threadIdx.x;
    const int tx = tid & 15, ty = tid >> 4;
    const int m0 = blockIdx.y * 128;
    const int n0 = blockIdx.x * 128;
    const int z = INTRA ? blockIdx.z : 0;

    const float* Wb = W1 + (size_t)z * (RIN * DRH);
    const float* bb = b1 + z * DRH;
    const float* extra = INTRA ? (g_bemb + z * DFE) : g_sfe;
    const int extra_ld = INTRA ? (NB * DFE) : DFE;
    float* ob = INTRA ? (g_ih + z * DRH) : g_bh;
    const int out_ld = INTRA ? (NB * DRH) : DRH;

    ull acc[8][4];
#pragma unroll
    for (int i = 0; i < 8; i++)
#pragma unroll
        for (int j = 0; j < 4; j++) acc[i][j] = 0ull;

    for (int k0 = 0; k0 < RIN; k0 += 16) {
#pragma unroll
        for (int l = 0; l < 2; l++) {
            int idx = l * 256 + tid;
            int row = idx >> 2, kq = idx & 3;
            int kg = k0 + kq * 4;
            float4 v;
            if (kg < D_HID)
                v = *(const float4*)&g_hnorm[(size_t)(m0 + row) * D_HID + kg];
            else
                v = *(const float4*)&extra[(size_t)(m0 + row) * extra_ld + (kg - D_HID)];
            As[kq * 4 + 0][row] = v.x; As[kq * 4 + 1][row] = v.y;
            As[kq * 4 + 2][row] = v.z; As[kq * 4 + 3][row] = v.w;
        }
#pragma unroll
        for (int l = 0; l < 2; l++) {
            int idx = l * 256 + tid;
            int kr = idx >> 5, nq = idx & 31;
            *(float4*)&Bs[kr][nq * 4] =
                *(const float4*)&Wb[(size_t)(k0 + kr) * DRH + n0 + nq * 4];
        }
        __syncthreads();
#pragma unroll
        for (int kk = 0; kk < 16; kk++) {
            float4 a0 = *(const float4*)&As[kk][ty * 4];
            float4 a1 = *(const float4*)&As[kk][64 + ty * 4];
            ull b00 = *(const ull*)&Bs[kk][tx * 4];
            ull b01 = *(const ull*)&Bs[kk][tx * 4 + 2];
            ull b10 = *(const ull*)&Bs[kk][64 + tx * 4];
            ull b11 = *(const ull*)&Bs[kk][64 + tx * 4 + 2];
            float ar[8] = {a0.x, a0.y, a0.z, a0.w, a1.x, a1.y, a1.z, a1.w};
#pragma unroll
            for (int i = 0; i < 8; i++) {
                ull a2 = pk2(ar[i], ar[i]);
                acc[i][0] = ffma2(a2, b00, acc[i][0]);
                acc[i][1] = ffma2(a2, b01, acc[i][1]);
                acc[i][2] = ffma2(a2, b10, acc[i][2]);
                acc[i][3] = ffma2(a2, b11, acc[i][3]);
            }
        }
        __syncthreads();
    }
#pragma unroll
    for (int i = 0; i < 8; i++) {
        int row = m0 + ((i < 4) ? (ty * 4 + i) : (64 + ty * 4 + (i - 4)));
#pragma unroll
        for (int j2 = 0; j2 < 4; j2++) {
            int c = (j2 < 2) ? (tx * 4 + j2 * 2) : (64 + tx * 4 + (j2 - 2) * 2);
            int n = n0 + c;
            float2 v = upk2(acc[i][j2]);
            float2 o;
            o.x = gelu_f(v.x + bb[n]);
            o.y = gelu_f(v.y + bb[n + 1]);
            *(float2*)&ob[(size_t)row * out_ld + n] = o;
        }
    }
}

// ---------------------------------------------------------------------------
// Kernel 4: bundle+intra logits, top-2 softmaxes, gate weights/logits outputs
// ---------------------------------------------------------------------------
__device__ __forceinline__ void top2sm4(const float* s, float* w) {
    float m1 = fmaxf(fmaxf(s[0], s[1]), fmaxf(s[2], s[3]));
    float m2 = -3.0e38f;
    bool used = false;
#pragma unroll
    for (int i = 0; i < 4; i++) {
        if (!used && s[i] == m1) used = true;
        else m2 = fmaxf(m2, s[i]);
    }
    float e[4];
    float den = 0.f;
#pragma unroll
    for (int i = 0; i < 4; i++) {
        e[i] = (s[i] >= m2) ? expf(s[i] - m1) : 0.f;
        den += e[i];
    }
    float inv = 1.0f / den;
#pragma unroll
    for (int i = 0; i < 4; i++) w[i] = e[i] * inv;
}

__global__ void __launch_bounds__(128) gate_kernel(
    const float* __restrict__ br_W2, const float* __restrict__ br_b2,
    const float* __restrict__ ir_W2, const float* __restrict__ ir_b2,
    float* __restrict__ out)
{
    const int t = blockIdx.x;
    const int tid = threadIdx.x;
    __shared__ float sbh[DRH];
    __shared__ float sih[NB * DRH];
    __shared__ float slog[20];

    for (int i = tid; i < DRH; i += 128) sbh[i] = g_bh[(size_t)t * DRH + i];
    for (int i = tid; i < NB * DRH; i += 128) sih[i] = g_ih[(size_t)t * NB * DRH + i];
    __syncthreads();

    const int w = tid >> 5, lane = tid & 31;
    for (int d = w; d < 20; d += 4) {
        float s = 0.f;
        if (d < 4) {
            for (int k = lane; k < DRH; k += 32) s += sbh[k] * br_W2[k * NB + d];
        } else {
            int g = (d - 4) >> 2, e = (d - 4) & 3;
            const float* w2 = ir_W2 + g * DRH * ES;
            const float* ihg = sih + g * DRH;
            for (int k = lane; k < DRH; k += 32) s += ihg[k] * w2[k * ES + e];
        }
#pragma unroll
        for (int off = 16; off; off >>= 1) s += __shfl_xor_sync(0xffffffffu, s, off);
        if (lane == 0) slog[d] = s + ((d < 4) ? br_b2[d] : ir_b2[d - 4]);
    }
    __syncthreads();

    if (tid == 0) {
        float bl[4], bw[4], il[16], iw[16];
#pragma unroll
        for (int i = 0; i < 4; i++) bl[i] = slog[i];
#pragma unroll
        for (int i = 0; i < 16; i++) il[i] = slog[4 + i];
        top2sm4(bl, bw);
#pragma unroll
        for (int g = 0; g < 4; g++) top2sm4(&il[g * 4], &iw[g * 4]);
#pragma unroll
        for (int g = 0; g < 4; g++) {
            out[OFF_BW + (size_t)t * NB + g] = bw[g];
            out[OFF_BL + (size_t)t * NB + g] = bl[g];
#pragma unroll
            for (int e = 0; e < 4; e++) {
                int idx = g * 4 + e;
                float gw = bw[g] * iw[idx];
                out[OFF_GW + (size_t)t * NE + idx] = gw;
                out[OFF_GL + (size_t)t * NE + idx] = bl[g] + il[idx];
                g_gate[(size_t)t * NE + idx] = gw;
            }
        }
    }
}

// ---------------------------------------------------------------------------
// Kernel 5: expert GEMM1  eh[t, e*512+h] = gate[t,e]*gelu(h_norm@W1[e] + b1)
// N = 16*512 = 8192 columns; each 128-col tile lies inside one expert.
// ---------------------------------------------------------------------------
__global__ void __launch_bounds__(256) ex1_gemm(
    const float* __restrict__ ex_W1, const float* __restrict__ ex_b1)
{
    __shared__ float As[16][132];
    __shared__ float Bs[16][128];
    const int tid = threadIdx.x;
    const int tx = tid & 15, ty = tid >> 4;
    const int m0 = blockIdx.y * 128;
    const int n0g = blockIdx.x * 128;
    const int e = n0g >> 9;
    const int c0 = n0g & 511;
    const float* Bb = ex_W1 + (size_t)e * (D_HID * DEH) + c0;

    ull acc[8][4];
#pragma unroll
    for (int i = 0; i < 8; i++)
#pragma unroll
        for (int j = 0; j < 4; j++) acc[i][j] = 0ull;

    for (int k0 = 0; k0 < D_HID; k0 += 16) {
#pragma unroll
        for (int l = 0; l < 2; l++) {
            int idx = l * 256 + tid;
            int row = idx >> 2, kq = idx & 3;
            float4 v = *(const float4*)&g_hnorm[(size_t)(m0 + row) * D_HID + k0 + kq * 4];
            As[kq * 4 + 0][row] = v.x; As[kq * 4 + 1][row] = v.y;
            As[kq * 4 + 2][row] = v.z; As[kq * 4 + 3][row] = v.w;
        }
#pragma unroll
        for (int l = 0; l < 2; l++) {
            int idx = l * 256 + tid;
            int kr = idx >> 5, nq = idx & 31;
            *(float4*)&Bs[kr][nq * 4] =
                *(const float4*)&Bb[(size_t)(k0 + kr) * DEH + nq * 4];
        }
        __syncthreads();
#pragma unroll
        for (int kk = 0; kk < 16; kk++) {
            float4 a0 = *(const float4*)&As[kk][ty * 4];
            float4 a1 = *(const float4*)&As[kk][64 + ty * 4];
            ull b00 = *(const ull*)&Bs[kk][tx * 4];
            ull b01 = *(const ull*)&Bs[kk][tx * 4 + 2];
            ull b10 = *(const ull*)&Bs[kk][64 + tx * 4];
            ull b11 = *(const ull*)&Bs[kk][64 + tx * 4 + 2];
            float ar[8] = {a0.x, a0.y, a0.z, a0.w, a1.x, a1.y, a1.z, a1.w};
#pragma unroll
            for (int i = 0; i < 8; i++) {
                ull a2 = pk2(ar[i], ar[i]);
                acc[i][0] = ffma2(a2, b00, acc[i][0]);
                acc[i][1] = ffma2(a2, b01, acc[i][1]);
                acc[i][2] = ffma2(a2, b10, acc[i][2]);
                acc[i][3] = ffma2(a2, b11, acc[i][3]);
            }
        }
        __syncthreads();
    }
#pragma unroll
    for (int i = 0; i < 8; i++) {
        int row = m0 + ((i < 4) ? (ty * 4 + i) : (64 + ty * 4 + (i - 4)));
        float gv = g_gate[(size_t)row * NE + e];
#pragma unroll
        for (int j2 = 0; j2 < 4; j2++) {
            int c = (j2 < 2) ? (tx * 4 + j2 * 2) : (64 + tx * 4 + (j2 - 2) * 2);
            int ng = n0g + c;
            float2 v = upk2(acc[i][j2]);
            float2 o;
            o.x = gelu_f(v.x + ex_b1[ng]) * gv;   // ex_b1 is flat [16*512]
            o.y = gelu_f(v.y + ex_b1[ng + 1]) * gv;
            *(float2*)&g_eh[(size_t)row * NEH + ng] = o;
        }
    }
}

// ---------------------------------------------------------------------------
// Kernel 6: expert GEMM2 + combine.
// delta[t,d] = sum_{e,k} eh_scaled[t,e*512+k] * W2[e,k,d] + sum_e g[t,e]*b2[e,d]
// ex_W2 [16,512,1024] flattens to a plain [8192,1024] row-major B.
// next_hidden = hidden + alpha*delta. Writes both big outputs.
// ---------------------------------------------------------------------------
__global__ void __launch_bounds__(256) ex2_gemm(
    const float* __restrict__ ex_W2, const float* __restrict__ ex_b2,
    const float* __restrict__ hidden, const float* __restrict__ alpha_p,
    float* __restrict__ out)
{
    __shared__ float As[16][132];
    __shared__ float Bs[16][128];
    const int tid = threadIdx.x;
    const int tx = tid & 15, ty = tid >> 4;
    const int m0 = blockIdx.y * 128;
    const int n0 = blockIdx.x * 128;

    ull acc[8][4];
#pragma unroll
    for (int i = 0; i < 8; i++)
#pragma unroll
        for (int j = 0; j < 4; j++) acc[i][j] = 0ull;

    for (int k0 = 0; k0 < NEH; k0 += 16) {
#pragma unroll
        for (int l = 0; l < 2; l++) {
            int idx = l * 256 + tid;
            int row = idx >> 2, kq = idx & 3;
            float4 v = *(const float4*)&g_eh[(size_t)(m0 + row) * NEH + k0 + kq * 4];
            As[kq * 4 + 0][row] = v.x; As[kq * 4 + 1][row] = v.y;
            As[kq * 4 + 2][row] = v.z; As[kq * 4 + 3][row] = v.w;
        }
#pragma unroll
        for (int l = 0; l < 2; l++) {
            int idx = l * 256 + tid;
            int kr = idx >> 5, nq = idx & 31;
            *(float4*)&Bs[kr][nq * 4] =
                *(const float4*)&ex_W2[(size_t)(k0 + kr) * D_HID + n0 + nq * 4];
        }
        __syncthreads();
#pragma unroll
        for (int kk = 0; kk < 16; kk++) {
            float4 a0 = *(const float4*)&As[kk][ty * 4];
            float4 a1 = *(const float4*)&As[kk][64 + ty * 4];
            ull b00 = *(const ull*)&Bs[kk][tx * 4];
            ull b01 = *(const ull*)&Bs[kk][tx * 4 + 2];
            ull b10 = *(const ull*)&Bs[kk][64 + tx * 4];
            ull b11 = *(const ull*)&Bs[kk][64 + tx * 4 + 2];
            float ar[8] = {a0.x, a0.y, a0.z, a0.w, a1.x, a1.y, a1.z, a1.w};
#pragma unroll
            for (int i = 0; i < 8; i++) {
                ull a2 = pk2(ar[i], ar[i]);
                acc[i][0] = ffma2(a2, b00, acc[i][0]);
                acc[i][1] = ffma2(a2, b01, acc[i][1]);
                acc[i][2] = ffma2(a2, b10, acc[i][2]);
                acc[i][3] = ffma2(a2, b11, acc[i][3]);
            }
        }
        __syncthreads();
    }

    const float alpha = *alpha_p;
#pragma unroll
    for (int i = 0; i < 8; i++) {
        int row = m0 + ((i < 4) ? (ty * 4 + i) : (64 + ty * 4 + (i - 4)));
        float g16[16];
#pragma unroll
        for (int e = 0; e < NE; e++) g16[e] = g_gate[(size_t)row * NE + e];
#pragma unroll
        for (int j2 = 0; j2 < 4; j2++) {
            int c = (j2 < 2) ? (tx * 4 + j2 * 2) : (64 + tx * 4 + (j2 - 2) * 2);
            int n = n0 + c;
            float2 v = upk2(acc[i][j2]);
            float b0 = 0.f, b1v = 0.f;
#pragma unroll
            for (int e = 0; e < NE; e++) {
                b0  = fmaf(g16[e], ex_b2[e * D_HID + n], b0);
                b1v = fmaf(g16[e], ex_b2[e * D_HID + n + 1], b1v);
            }
            float d0 = v.x + b0;
            float d1 = v.y + b1v;
            float2 h = *(const float2*)&hidden[(size_t)row * D_HID + n];
            float2 nh; nh.x = h.x + alpha * d0; nh.y = h.y + alpha * d1;
            float2 sd; sd.x = d0; sd.y = d1;
            *(float2*)&out[OFF_NH + (size_t)row * D_HID + n] = nh;
            *(float2*)&out[OFF_SD + (size_t)row * D_HID + n] = sd;
        }
    }
}

// ---------------------------------------------------------------------------
// launch
// ---------------------------------------------------------------------------
extern "C" void kernel_launch(void* const* d_in, const int* in_sizes, int n_in,
                              void* d_out, int out_size)
{
    const float* hidden  = (const float*)d_in[0];
    const float* feat    = (const float*)d_in[1];
    const float* ln_g    = (const float*)d_in[2];
    const float* ln_b    = (const float*)d_in[3];
    const float* stage_W = (const float*)d_in[4];
    const float* stage_b = (const float*)d_in[5];
    const float* bproj_W = (const float*)d_in[6];
    const float* bproj_b = (const float*)d_in[7];
    const float* br_W1   = (const float*)d_in[8];
    const float* br_b1   = (const float*)d_in[9];
    const float* br_W2   = (const float*)d_in[10];
    const float* br_b2   = (const float*)d_in[11];
    const float* ir_W1   = (const float*)d_in[12];
    const float* ir_b1   = (const float*)d_in[13];
    const float* ir_W2   = (const float*)d_in[14];
    const float* ir_b2   = (const float*)d_in[15];
    const float* ex_W1   = (const float*)d_in[16];
    const float* ex_b1   = (const float*)d_in[17];
    const float* ex_W2   = (const float*)d_in[18];
    const float* ex_b2   = (const float*)d_in[19];
    const float* alpha   = (const float*)d_in[20];
    float* out = (float*)d_out;

    prep_kernel<<<M_TOK, 256>>>(hidden, feat, ln_g, ln_b,
                                stage_W, stage_b, bproj_W, bproj_b);

    {
        dim3 g(DRH / 128, M_TOK / 128, 1);
        router_gemm<0><<<g, 256>>>(br_W1, br_b1);
    }
    {
        dim3 g(DRH / 128, M_TOK / 128, NB);
        router_gemm<1><<<g, 256>>>(ir_W1, ir_b1);
    }

    gate_kernel<<<M_TOK, 128>>>(br_W2, br_b2, ir_W2, ir_b2, out);

    {
        dim3 g(NEH / 128, M_TOK / 128, 1);
        ex1_gemm<<<g, 256>>>(ex_W1, ex_b1);
    }
    {
        dim3 g(D_HID / 128, M_TOK / 128, 1);
        ex2_gemm<<<g, 256>>>(ex_W2, ex_b2, hidden, alpha, out);
    }
}

// round 8
// speedup vs baseline: 2.2164x; 2.2164x over previous
#include <cuda_runtime.h>
#include <cuda_bf16.h>
#include <cstdint>

#define M_TOK 8192
#define D_HID 1024
#define F_FEAT 64
#define DFE 128
#define RIN 1152
#define DRH 256
#define NB 4
#define FPB 16
#define ES 4
#define NE 16
#define DEH 512
#define NEH (NE * DEH)

#define OFF_NH 0
#define OFF_GW (M_TOK * D_HID)
#define OFF_GL (OFF_GW + M_TOK * NE)
#define OFF_BW (OFF_GL + M_TOK * NE)
#define OFF_BL (OFF_BW + M_TOK * NB)
#define OFF_SD (OFF_BL + M_TOK * NB)

typedef unsigned long long ull;
typedef __nv_bfloat16 bf16;

// ------------------------- scratch ------------------------------------------
__device__ float g_hnorm[M_TOK * D_HID];
__device__ float g_sfe[M_TOK * DFE];
__device__ float g_bemb[M_TOK * NB * DFE];
__device__ float g_bh[M_TOK * DRH];
__device__ float g_ih[M_TOK * NB * DRH];
__device__ float g_gate[M_TOK * NE];
__device__ float g_gbias[M_TOK * D_HID];
__device__ bf16 g_ah[M_TOK * D_HID];
__device__ bf16 g_al[M_TOK * D_HID];
__device__ bf16 g_w1t_h[NEH * D_HID];     // [n][k] n=NEH, k=D_HID
__device__ bf16 g_w1t_l[NEH * D_HID];
__device__ bf16 g_w2t_h[D_HID * NEH];     // [n][k] n=D_HID, k=NEH
__device__ bf16 g_w2t_l[D_HID * NEH];
__device__ bf16 g_ehh[(size_t)M_TOK * NEH];
__device__ bf16 g_ehl[(size_t)M_TOK * NEH];

// ------------------------- helpers ------------------------------------------
__device__ __forceinline__ float gelu_f(float x) {
    return 0.5f * x * (1.0f + erff(x * 0.70710678118654752440f));
}
__device__ __forceinline__ ull ffma2(ull a, ull b, ull c) {
    ull d;
    asm("fma.rn.f32x2 %0, %1, %2, %3;" : "=l"(d) : "l"(a), "l"(b), "l"(c));
    return d;
}
__device__ __forceinline__ ull pk2(float x, float y) {
    ull r;
    asm("mov.b64 %0, {%1, %2};" : "=l"(r) : "f"(x), "f"(y));
    return r;
}
__device__ __forceinline__ float2 upk2(ull v) {
    float2 r;
    asm("mov.b64 {%0, %1}, %2;" : "=f"(r.x), "=f"(r.y) : "l"(v));
    return r;
}
__device__ __forceinline__ void split_bf16(float v, bf16& h, bf16& l) {
    h = __float2bfloat16(v);
    l = __float2bfloat16(v - __bfloat162float(h));
}
__device__ __forceinline__ uint32_t smem_u32(const void* p) {
    uint32_t a;
    asm("{ .reg .u64 t; cvta.to.shared.u64 t, %1; cvt.u32.u64 %0, t; }"
        : "=r"(a) : "l"(p));
    return a;
}
__device__ __forceinline__ void cpa16(uint32_t s, const void* g) {
    asm volatile("cp.async.cg.shared.global [%0], [%1], 16;" :: "r"(s), "l"(g));
}
#define CP_COMMIT() asm volatile("cp.async.commit_group;" ::: "memory")
#define CP_WAIT1()  asm volatile("cp.async.wait_group 1;" ::: "memory")
#define CP_WAIT0()  asm volatile("cp.async.wait_group 0;" ::: "memory")

__device__ __forceinline__ void ldsm4(uint32_t* r, uint32_t addr) {
    asm volatile("ldmatrix.sync.aligned.m8n8.x4.shared.b16 {%0,%1,%2,%3}, [%4];"
        : "=r"(r[0]), "=r"(r[1]), "=r"(r[2]), "=r"(r[3]) : "r"(addr));
}
__device__ __forceinline__ void mma16816(float* c, const uint32_t* a, const uint32_t* b) {
    asm volatile("mma.sync.aligned.m16n8k16.row.col.f32.bf16.bf16.f32 "
        "{%0,%1,%2,%3}, {%4,%5,%6,%7}, {%8,%9}, {%0,%1,%2,%3};"
        : "+f"(c[0]), "+f"(c[1]), "+f"(c[2]), "+f"(c[3])
        : "r"(a[0]), "r"(a[1]), "r"(a[2]), "r"(a[3]), "r"(b[0]), "r"(b[1]));
}

// ---------------------------------------------------------------------------
// Kernel 1: LN (+bf16 split) + stage/bundle embeddings
// ---------------------------------------------------------------------------
__global__ void __launch_bounds__(256) prep_kernel(
    const float* __restrict__ hidden, const float* __restrict__ feat,
    const float* __restrict__ ln_g, const float* __restrict__ ln_b,
    const float* __restrict__ stage_W, const float* __restrict__ stage_b,
    const float* __restrict__ bproj_W, const float* __restrict__ bproj_b)
{
    const int t = blockIdx.x, tid = threadIdx.x;
    __shared__ float red[256];
    __shared__ float sfeat[F_FEAT];
    const float* hrow = hidden + (size_t)t * D_HID;
    float x[4], s = 0.f;
#pragma unroll
    for (int i = 0; i < 4; i++) { x[i] = hrow[tid + 256 * i]; s += x[i]; }
    if (tid < F_FEAT) sfeat[tid] = feat[(size_t)t * F_FEAT + tid];
    red[tid] = s;
    __syncthreads();
    for (int off = 128; off > 0; off >>= 1) {
        if (tid < off) red[tid] += red[tid + off];
        __syncthreads();
    }
    const float mu = red[0] * (1.0f / 1024.0f);
    __syncthreads();
    float v = 0.f;
#pragma unroll
    for (int i = 0; i < 4; i++) { float d = x[i] - mu; v += d * d; }
    red[tid] = v;
    __syncthreads();
    for (int off = 128; off > 0; off >>= 1) {
        if (tid < off) red[tid] += red[tid + off];
        __syncthreads();
    }
    const float rstd = rsqrtf(red[0] * (1.0f / 1024.0f) + 1e-5f);
#pragma unroll
    for (int i = 0; i < 4; i++) {
        int d = tid + 256 * i;
        float hv = (x[i] - mu) * rstd * ln_g[d] + ln_b[d];
        g_hnorm[(size_t)t * D_HID + d] = hv;
        bf16 hi, lo; split_bf16(hv, hi, lo);
        g_ah[(size_t)t * D_HID + d] = hi;
        g_al[(size_t)t * D_HID + d] = lo;
    }
    if (tid < DFE) {
        float acc = stage_b[tid];
#pragma unroll
        for (int f = 0; f < F_FEAT; f++) acc += sfeat[f] * stage_W[f * DFE + tid];
        g_sfe[(size_t)t * DFE + tid] = acc;
    }
    for (int idx = tid; idx < NB * DFE; idx += 256) {
        int g = idx >> 7, j = idx & 127;
        float acc = bproj_b[g * DFE + j];
#pragma unroll
        for (int f = 0; f < FPB; f++)
            acc += sfeat[g * FPB + f] * bproj_W[(g * FPB + f) * DFE + j];
        g_bemb[(size_t)t * (NB * DFE) + idx] = acc;
    }
}

// ---------------------------------------------------------------------------
// Transpose + bf16 split.  W=1: ex_W1[z] (1024x512) -> w1t [n=z*512+c][k];
// W=2: ex_W2 flat (8192x1024) -> w2t [n=1024][k=8192].
// ---------------------------------------------------------------------------
template <int W>
__global__ void __launch_bounds__(256) transpose_split(const float* __restrict__ src)
{
    __shared__ float tl[32][33];
    const int z = blockIdx.z;
    const int C = (W == 1) ? DEH : D_HID;
    const size_t dld = (W == 1) ? D_HID : NEH;
    const float* s = src + (size_t)z * ((W == 1) ? (D_HID * DEH) : 0);
    const int r0 = blockIdx.y * 32, c0 = blockIdx.x * 32;
    const int tx = threadIdx.x & 31, ty = threadIdx.x >> 5;
#pragma unroll
    for (int i = 0; i < 4; i++)
        tl[ty + i * 8][tx] = s[(size_t)(r0 + ty + i * 8) * C + c0 + tx];
    __syncthreads();
#pragma unroll
    for (int i = 0; i < 4; i++) {
        int c = c0 + ty + i * 8;
        float v = tl[tx][ty + i * 8];
        size_t o = ((size_t)(W == 1 ? z * DEH : 0) + c) * dld + r0 + tx;
        bf16 hi, lo; split_bf16(v, hi, lo);
        if (W == 1) { g_w1t_h[o] = hi; g_w1t_l[o] = lo; }
        else        { g_w2t_h[o] = hi; g_w2t_l[o] = lo; }
    }
}

// ---------------------------------------------------------------------------
// Router GEMM1 (FFMA2) — unchanged proven path
// ---------------------------------------------------------------------------
template <int INTRA>
__global__ void __launch_bounds__(256) router_gemm(
    const float* __restrict__ W1, const float* __restrict__ b1)
{
    __shared__ float As[16][132];
    __shared__ float Bs[16][128];
    const int tid = threadIdx.x;
    const int tx = tid & 15, ty = tid >> 4;
    const int m0 = blockIdx.y * 128, n0 = blockIdx.x * 128;
    const int z = INTRA ? blockIdx.z : 0;
    const float* Wb = W1 + (size_t)z * (RIN * DRH);
    const float* bb = b1 + z * DRH;
    const float* extra = INTRA ? (g_bemb + z * DFE) : g_sfe;
    const int extra_ld = INTRA ? (NB * DFE) : DFE;
    float* ob = INTRA ? (g_ih + z * DRH) : g_bh;
    const int out_ld = INTRA ? (NB * DRH) : DRH;

    ull acc[8][4];
#pragma unroll
    for (int i = 0; i < 8; i++)
#pragma unroll
        for (int j = 0; j < 4; j++) acc[i][j] = 0ull;

    for (int k0 = 0; k0 < RIN; k0 += 16) {
#pragma unroll
        for (int l = 0; l < 2; l++) {
            int idx = l * 256 + tid;
            int row = idx >> 2, kq = idx & 3;
            int kg = k0 + kq * 4;
            float4 v;
            if (kg < D_HID)
                v = *(const float4*)&g_hnorm[(size_t)(m0 + row) * D_HID + kg];
            else
                v = *(const float4*)&extra[(size_t)(m0 + row) * extra_ld + (kg - D_HID)];
            As[kq * 4 + 0][row] = v.x; As[kq * 4 + 1][row] = v.y;
            As[kq * 4 + 2][row] = v.z; As[kq * 4 + 3][row] = v.w;
        }
#pragma unroll
        for (int l = 0; l < 2; l++) {
            int idx = l * 256 + tid;
            int kr = idx >> 5, nq = idx & 31;
            *(float4*)&Bs[kr][nq * 4] =
                *(const float4*)&Wb[(size_t)(k0 + kr) * DRH + n0 + nq * 4];
        }
        __syncthreads();
#pragma unroll
        for (int kk = 0; kk < 16; kk++) {
            float4 a0 = *(const float4*)&As[kk][ty * 4];
            float4 a1 = *(const float4*)&As[kk][64 + ty * 4];
            ull b00 = *(const ull*)&Bs[kk][tx * 4];
            ull b01 = *(const ull*)&Bs[kk][tx * 4 + 2];
            ull b10 = *(const ull*)&Bs[kk][64 + tx * 4];
            ull b11 = *(const ull*)&Bs[kk][64 + tx * 4 + 2];
            float ar[8] = {a0.x, a0.y, a0.z, a0.w, a1.x, a1.y, a1.z, a1.w};
#pragma unroll
            for (int i = 0; i < 8; i++) {
                ull a2 = pk2(ar[i], ar[i]);
                acc[i][0] = ffma2(a2, b00, acc[i][0]);
                acc[i][1] = ffma2(a2, b01, acc[i][1]);
                acc[i][2] = ffma2(a2, b10, acc[i][2]);
                acc[i][3] = ffma2(a2, b11, acc[i][3]);
            }
        }
        __syncthreads();
    }
#pragma unroll
    for (int i = 0; i < 8; i++) {
        int row = m0 + ((i < 4) ? (ty * 4 + i) : (64 + ty * 4 + (i - 4)));
#pragma unroll
        for (int j2 = 0; j2 < 4; j2++) {
            int c = (j2 < 2) ? (tx * 4 + j2 * 2) : (64 + tx * 4 + (j2 - 2) * 2);
            int n = n0 + c;
            float2 v = upk2(acc[i][j2]);
            float2 o;
            o.x = gelu_f(v.x + bb[n]);
            o.y = gelu_f(v.y + bb[n + 1]);
            *(float2*)&ob[(size_t)row * out_ld + n] = o;
        }
    }
}

// ---------------------------------------------------------------------------
// Gate kernel
// ---------------------------------------------------------------------------
__device__ __forceinline__ void top2sm4(const float* s, float* w) {
    float m1 = fmaxf(fmaxf(s[0], s[1]), fmaxf(s[2], s[3]));
    float m2 = -3.0e38f;
    bool used = false;
#pragma unroll
    for (int i = 0; i < 4; i++) {
        if (!used && s[i] == m1) used = true;
        else m2 = fmaxf(m2, s[i]);
    }
    float e[4], den = 0.f;
#pragma unroll
    for (int i = 0; i < 4; i++) {
        e[i] = (s[i] >= m2) ? expf(s[i] - m1) : 0.f;
        den += e[i];
    }
    float inv = 1.0f / den;
#pragma unroll
    for (int i = 0; i < 4; i++) w[i] = e[i] * inv;
}

__global__ void __launch_bounds__(128) gate_kernel(
    const float* __restrict__ br_W2, const float* __restrict__ br_b2,
    const float* __restrict__ ir_W2, const float* __restrict__ ir_b2,
    float* __restrict__ out)
{
    const int t = blockIdx.x, tid = threadIdx.x;
    __shared__ float sbh[DRH];
    __shared__ float sih[NB * DRH];
    __shared__ float slog[20];
    for (int i = tid; i < DRH; i += 128) sbh[i] = g_bh[(size_t)t * DRH + i];
    for (int i = tid; i < NB * DRH; i += 128) sih[i] = g_ih[(size_t)t * NB * DRH + i];
    __syncthreads();
    const int w = tid >> 5, lane = tid & 31;
    for (int d = w; d < 20; d += 4) {
        float s = 0.f;
        if (d < 4) {
            for (int k = lane; k < DRH; k += 32) s += sbh[k] * br_W2[k * NB + d];
        } else {
            int g = (d - 4) >> 2, e = (d - 4) & 3;
            const float* w2 = ir_W2 + g * DRH * ES;
            const float* ihg = sih + g * DRH;
            for (int k = lane; k < DRH; k += 32) s += ihg[k] * w2[k * ES + e];
        }
#pragma unroll
        for (int off = 16; off; off >>= 1) s += __shfl_xor_sync(0xffffffffu, s, off);
        if (lane == 0) slog[d] = s + ((d < 4) ? br_b2[d] : ir_b2[d - 4]);
    }
    __syncthreads();
    if (tid == 0) {
        float bl[4], bw[4], il[16], iw[16];
#pragma unroll
        for (int i = 0; i < 4; i++) bl[i] = slog[i];
#pragma unroll
        for (int i = 0; i < 16; i++) il[i] = slog[4 + i];
        top2sm4(bl, bw);
#pragma unroll
        for (int g = 0; g < 4; g++) top2sm4(&il[g * 4], &iw[g * 4]);
#pragma unroll
        for (int g = 0; g < 4; g++) {
            out[OFF_BW + (size_t)t * NB + g] = bw[g];
            out[OFF_BL + (size_t)t * NB + g] = bl[g];
#pragma unroll
            for (int e = 0; e < 4; e++) {
                int idx = g * 4 + e;
                float gw = bw[g] * iw[idx];
                out[OFF_GW + (size_t)t * NE + idx] = gw;
                out[OFF_GL + (size_t)t * NE + idx] = bl[g] + il[idx];
                g_gate[(size_t)t * NE + idx] = gw;
            }
        }
    }
}

// gbias[t,d] = sum_e gate[t,e] * ex_b2[e,d]
__global__ void __launch_bounds__(256) gbias_kernel(const float* __restrict__ ex_b2)
{
    const int t = blockIdx.x;
    __shared__ float sg[NE];
    if (threadIdx.x < NE) sg[threadIdx.x] = g_gate[(size_t)t * NE + threadIdx.x];
    __syncthreads();
    const int d = threadIdx.x * 4;
    float4 a = {0.f, 0.f, 0.f, 0.f};
#pragma unroll
    for (int e = 0; e < NE; e++) {
        float4 b = *(const float4*)&ex_b2[e * D_HID + d];
        a.x = fmaf(sg[e], b.x, a.x); a.y = fmaf(sg[e], b.y, a.y);
        a.z = fmaf(sg[e], b.z, a.z); a.w = fmaf(sg[e], b.w, a.w);
    }
    *(float4*)&g_gbias[(size_t)t * D_HID + d] = a;
}

// ---------------------------------------------------------------------------
// HMMA split-bf16 GEMM.  CTA 128x128, K-chunk 32, 8 warps (warp 64x32),
// cp.async double-buffered, ldmatrix non-trans (A [m][k], B [n][k]).
// EPI=1: ex1 (gelu(.+b1)*gate -> eh hi/lo).  EPI=2: ex2 (combine -> out).
// ---------------------------------------------------------------------------
#define LDT 40                        // padded row (32 + 8 bf16)
#define SAB (128 * LDT * 2)           // one matrix tile bytes = 10240
#define BUFB (4 * SAB)                // buffer bytes = 40960
#define DSM_MMA (2 * BUFB)            // 81920

__device__ __forceinline__ void load_chunk(
    uint32_t sbase, const bf16* __restrict__ Ah, const bf16* __restrict__ Al,
    const bf16* __restrict__ Bh, const bf16* __restrict__ Bl, int ldk, int tid)
{
#pragma unroll
    for (int i = 0; i < 2; i++) {
        int q = i * 256 + tid;                 // 0..511
        int row = q >> 2, seg = q & 3;
        uint32_t so = (uint32_t)(row * LDT + seg * 8) * 2;
        size_t go = (size_t)row * ldk + seg * 8;
        cpa16(sbase + so,            Ah + go);
        cpa16(sbase + SAB + so,      Al + go);
        cpa16(sbase + 2 * SAB + so,  Bh + go);
        cpa16(sbase + 3 * SAB + so,  Bl + go);
    }
}

template <int EPI>
__global__ void __launch_bounds__(256) mma_kernel(
    const float* __restrict__ b1, const float* __restrict__ hidden,
    const float* __restrict__ alpha_p, float* __restrict__ out)
{
    extern __shared__ bf16 dsm[];
    const uint32_t sbase = smem_u32(dsm);
    const int tid = threadIdx.x;
    const int wid = tid >> 5, lane = tid & 31;
    const int m0 = blockIdx.y * 128;
    const int n0 = blockIdx.x * 128;

    const bf16* Ah = ((EPI == 1) ? g_ah : g_ehh) + (size_t)m0 * ((EPI == 1) ? D_HID : NEH);
    const bf16* Al = ((EPI == 1) ? g_al : g_ehl) + (size_t)m0 * ((EPI == 1) ? D_HID : NEH);
    const bf16* Bh = ((EPI == 1) ? g_w1t_h : g_w2t_h) + (size_t)n0 * ((EPI == 1) ? D_HID : NEH);
    const bf16* Bl = ((EPI == 1) ? g_w1t_l : g_w2t_l) + (size_t)n0 * ((EPI == 1) ? D_HID : NEH);
    const int ldk = (EPI == 1) ? D_HID : NEH;
    const int nchunk = ldk / 32;

    const int mw = (wid >> 2) * 64;   // warp m-base within tile
    const int nw = (wid & 3) * 32;    // warp n-base within tile

    float acc[4][4][4];
#pragma unroll
    for (int a = 0; a < 4; a++)
#pragma unroll
        for (int b = 0; b < 4; b++)
#pragma unroll
            for (int c = 0; c < 4; c++) acc[a][b][c] = 0.f;

    load_chunk(sbase, Ah, Al, Bh, Bl, ldk, tid);
    CP_COMMIT();

    for (int ci = 0; ci < nchunk; ci++) {
        if (ci + 1 < nchunk) {
            load_chunk(sbase + ((ci + 1) & 1) * BUFB,
                       Ah + (ci + 1) * 32, Al + (ci + 1) * 32,
                       Bh + (ci + 1) * 32, Bl + (ci + 1) * 32, ldk, tid);
            CP_COMMIT();
            CP_WAIT1();
        } else {
            CP_WAIT0();
        }
        __syncthreads();

        const uint32_t ab = sbase + (ci & 1) * BUFB;
        const uint32_t bb = ab + 2 * SAB;
#pragma unroll
        for (int ks = 0; ks < 32; ks += 16) {
            uint32_t ah[4][4], al[4][4], bhf[2][4], blf[2][4];
#pragma unroll
            for (int mi = 0; mi < 4; mi++) {
                uint32_t ra = ab + (uint32_t)((mw + mi * 16 + (lane & 15)) * LDT
                                              + ks + ((lane >> 4) & 1) * 8) * 2;
                ldsm4(ah[mi], ra);
                ldsm4(al[mi], ra + SAB);
            }
#pragma unroll
            for (int pj = 0; pj < 2; pj++) {
                uint32_t rb = bb + (uint32_t)((nw + pj * 16 + ((lane >> 4) & 1) * 8
                                               + (lane & 7)) * LDT
                                              + ks + ((lane >> 3) & 1) * 8) * 2;
                ldsm4(bhf[pj], rb);
                ldsm4(blf[pj], rb + SAB);
            }
#pragma unroll
            for (int mi = 0; mi < 4; mi++)
#pragma unroll
                for (int nj = 0; nj < 4; nj++) {
                    const int pj = nj >> 1, sb = (nj & 1) * 2;
                    mma16816(acc[mi][nj], ah[mi], &bhf[pj][sb]);
                    mma16816(acc[mi][nj], ah[mi], &blf[pj][sb]);
                    mma16816(acc[mi][nj], al[mi], &bhf[pj][sb]);
                }
        }
        __syncthreads();
    }

    // ---------------- epilogue ----------------
    const int mfrag = mw + (lane >> 2);
    const int nfrag = nw + (lane & 3) * 2;

    if (EPI == 1) {
        const int e = n0 >> 9;
#pragma unroll
        for (int mi = 0; mi < 4; mi++) {
            const int r0 = m0 + mfrag + mi * 16;
            const float gv0 = g_gate[(size_t)r0 * NE + e];
            const float gv1 = g_gate[(size_t)(r0 + 8) * NE + e];
#pragma unroll
            for (int nj = 0; nj < 4; nj++) {
                const int ng = n0 + nfrag + nj * 8;
                const float* c = acc[mi][nj];
                float o0 = gelu_f(c[0] + b1[ng])     * gv0;
                float o1 = gelu_f(c[1] + b1[ng + 1]) * gv0;
                float o2 = gelu_f(c[2] + b1[ng])     * gv1;
                float o3 = gelu_f(c[3] + b1[ng + 1]) * gv1;
                bf16 h0, l0, h1, l1, h2, l2, h3, l3;
                split_bf16(o0, h0, l0); split_bf16(o1, h1, l1);
                split_bf16(o2, h2, l2); split_bf16(o3, h3, l3);
                *(__nv_bfloat162*)&g_ehh[(size_t)r0 * NEH + ng]       = __halves2bfloat162(h0, h1);
                *(__nv_bfloat162*)&g_ehl[(size_t)r0 * NEH + ng]       = __halves2bfloat162(l0, l1);
                *(__nv_bfloat162*)&g_ehh[(size_t)(r0 + 8) * NEH + ng] = __halves2bfloat162(h2, h3);
                *(__nv_bfloat162*)&g_ehl[(size_t)(r0 + 8) * NEH + ng] = __halves2bfloat162(l2, l3);
            }
        }
    } else {
        const float alpha = *alpha_p;
#pragma unroll
        for (int mi = 0; mi < 4; mi++) {
            const int r0 = m0 + mfrag + mi * 16;
#pragma unroll
            for (int nj = 0; nj < 4; nj++) {
                const int ng = n0 + nfrag + nj * 8;
                const float* c = acc[mi][nj];
#pragma unroll
                for (int h = 0; h < 2; h++) {
                    const int r = r0 + h * 8;
                    const size_t go = (size_t)r * D_HID + ng;
                    float2 gb = *(const float2*)&g_gbias[go];
                    float2 hv = *(const float2*)&hidden[go];
                    float2 sd, nh;
                    sd.x = c[h * 2]     + gb.x;
                    sd.y = c[h * 2 + 1] + gb.y;
                    nh.x = hv.x + alpha * sd.x;
                    nh.y = hv.y + alpha * sd.y;
                    *(float2*)&out[OFF_SD + go] = sd;
                    *(float2*)&out[OFF_NH + go] = nh;
                }
            }
        }
    }
}

// ---------------------------------------------------------------------------
extern "C" void kernel_launch(void* const* d_in, const int* in_sizes, int n_in,
                              void* d_out, int out_size)
{
    const float* hidden  = (const float*)d_in[0];
    const float* feat    = (const float*)d_in[1];
    const float* ln_g    = (const float*)d_in[2];
    const float* ln_b    = (const float*)d_in[3];
    const float* stage_W = (const float*)d_in[4];
    const float* stage_b = (const float*)d_in[5];
    const float* bproj_W = (const float*)d_in[6];
    const float* bproj_b = (const float*)d_in[7];
    const float* br_W1   = (const float*)d_in[8];
    const float* br_b1   = (const float*)d_in[9];
    const float* br_W2   = (const float*)d_in[10];
    const float* br_b2   = (const float*)d_in[11];
    const float* ir_W1   = (const float*)d_in[12];
    const float* ir_b1   = (const float*)d_in[13];
    const float* ir_W2   = (const float*)d_in[14];
    const float* ir_b2   = (const float*)d_in[15];
    const float* ex_W1   = (const float*)d_in[16];
    const float* ex_b1   = (const float*)d_in[17];
    const float* ex_W2   = (const float*)d_in[18];
    const float* ex_b2   = (const float*)d_in[19];
    const float* alpha   = (const float*)d_in[20];
    float* out = (float*)d_out;

    cudaFuncSetAttribute(mma_kernel<1>, cudaFuncAttributeMaxDynamicSharedMemorySize, DSM_MMA);
    cudaFuncSetAttribute(mma_kernel<2>, cudaFuncAttributeMaxDynamicSharedMemorySize, DSM_MMA);

    prep_kernel<<<M_TOK, 256>>>(hidden, feat, ln_g, ln_b,
                                stage_W, stage_b, bproj_W, bproj_b);
    {
        dim3 g(DEH / 32, D_HID / 32, NE);
        transpose_split<1><<<g, 256>>>(ex_W1);
    }
    {
        dim3 g(D_HID / 32, NEH / 32, 1);
        transpose_split<2><<<g, 256>>>(ex_W2);
    }
    {
        dim3 g(DRH / 128, M_TOK / 128, 1);
        router_gemm<0><<<g, 256>>>(br_W1, br_b1);
    }
    {
        dim3 g(DRH / 128, M_TOK / 128, NB);
        router_gemm<1><<<g, 256>>>(ir_W1, ir_b1);
    }
    gate_kernel<<<M_TOK, 128>>>(br_W2, br_b2, ir_W2, ir_b2, out);
    gbias_kernel<<<M_TOK, 256>>>(ex_b2);
    {
        dim3 g(NEH / 128, M_TOK / 128, 1);
        mma_kernel<1><<<g, 256, DSM_MMA>>>(ex_b1, hidden, alpha, out);
    }
    {
        dim3 g(D_HID / 128, M_TOK / 128, 1);
        mma_kernel<2><<<g, 256, DSM_MMA>>>(ex_b1, hidden, alpha, out);
    }
}

// round 9
// speedup vs baseline: 2.4763x; 1.1173x over previous
#include <cuda_runtime.h>
#include <cuda_bf16.h>
#include <cstdint>

#define M_TOK 8192
#define D_HID 1024
#define F_FEAT 64
#define DFE 128
#define RIN 1152
#define DRH 256
#define NB 4
#define FPB 16
#define ES 4
#define NE 16
#define DEH 512
#define NEH (NE * DEH)

#define OFF_NH 0
#define OFF_GW (M_TOK * D_HID)
#define OFF_GL (OFF_GW + M_TOK * NE)
#define OFF_BW (OFF_GL + M_TOK * NE)
#define OFF_BL (OFF_BW + M_TOK * NB)
#define OFF_SD (OFF_BL + M_TOK * NB)

typedef unsigned long long ull;
typedef __nv_bfloat16 bf16;

// ------------------------- scratch ------------------------------------------
__device__ float g_bh[M_TOK * DRH];
__device__ float g_ih[M_TOK * NB * DRH];
__device__ float g_gate[M_TOK * NE];
__device__ float g_gbias[M_TOK * D_HID];
__device__ bf16 g_ah[M_TOK * D_HID];
__device__ bf16 g_al[M_TOK * D_HID];
__device__ bf16 g_sfe_h[M_TOK * DFE];
__device__ bf16 g_sfe_l[M_TOK * DFE];
__device__ bf16 g_bemb_h[M_TOK * NB * DFE];
__device__ bf16 g_bemb_l[M_TOK * NB * DFE];
__device__ bf16 g_wbr_h[DRH * RIN];       // br_W1^T  [n][k]
__device__ bf16 g_wbr_l[DRH * RIN];
__device__ bf16 g_wir_h[NB * DRH * RIN];  // ir_W1^T  [g*DRH+n][k]
__device__ bf16 g_wir_l[NB * DRH * RIN];
__device__ bf16 g_w1t_h[NEH * D_HID];     // ex_W1^T  [n][k]
__device__ bf16 g_w1t_l[NEH * D_HID];
__device__ bf16 g_w2t_h[D_HID * NEH];     // ex_W2^T  [n][k]
__device__ bf16 g_w2t_l[D_HID * NEH];
__device__ bf16 g_ehh[(size_t)M_TOK * NEH];
__device__ bf16 g_ehl[(size_t)M_TOK * NEH];

// ------------------------- helpers ------------------------------------------
__device__ __forceinline__ float gelu_f(float x) {
    return 0.5f * x * (1.0f + erff(x * 0.70710678118654752440f));
}
__device__ __forceinline__ void split_bf16(float v, bf16& h, bf16& l) {
    h = __float2bfloat16(v);
    l = __float2bfloat16(v - __bfloat162float(h));
}
__device__ __forceinline__ uint32_t smem_u32(const void* p) {
    uint32_t a;
    asm("{ .reg .u64 t; cvta.to.shared.u64 t, %1; cvt.u32.u64 %0, t; }"
        : "=r"(a) : "l"(p));
    return a;
}
__device__ __forceinline__ void cpa16(uint32_t s, const void* g) {
    asm volatile("cp.async.cg.shared.global [%0], [%1], 16;" :: "r"(s), "l"(g));
}
#define CP_COMMIT() asm volatile("cp.async.commit_group;" ::: "memory")
#define CP_WAIT1()  asm volatile("cp.async.wait_group 1;" ::: "memory")
#define CP_WAIT0()  asm volatile("cp.async.wait_group 0;" ::: "memory")

__device__ __forceinline__ void ldsm4(uint32_t* r, uint32_t addr) {
    asm volatile("ldmatrix.sync.aligned.m8n8.x4.shared.b16 {%0,%1,%2,%3}, [%4];"
        : "=r"(r[0]), "=r"(r[1]), "=r"(r[2]), "=r"(r[3]) : "r"(addr));
}
__device__ __forceinline__ void mma16816(float* c, const uint32_t* a, const uint32_t* b) {
    asm volatile("mma.sync.aligned.m16n8k16.row.col.f32.bf16.bf16.f32 "
        "{%0,%1,%2,%3}, {%4,%5,%6,%7}, {%8,%9}, {%0,%1,%2,%3};"
        : "+f"(c[0]), "+f"(c[1]), "+f"(c[2]), "+f"(c[3])
        : "r"(a[0]), "r"(a[1]), "r"(a[2]), "r"(a[3]), "r"(b[0]), "r"(b[1]));
}

// ---------------------------------------------------------------------------
// Kernel 1: LN (bf16 split only) + stage/bundle embeddings (bf16 split)
// ---------------------------------------------------------------------------
__global__ void __launch_bounds__(256) prep_kernel(
    const float* __restrict__ hidden, const float* __restrict__ feat,
    const float* __restrict__ ln_g, const float* __restrict__ ln_b,
    const float* __restrict__ stage_W, const float* __restrict__ stage_b,
    const float* __restrict__ bproj_W, const float* __restrict__ bproj_b)
{
    const int t = blockIdx.x, tid = threadIdx.x;
    __shared__ float red[256];
    __shared__ float sfeat[F_FEAT];
    const float* hrow = hidden + (size_t)t * D_HID;
    float x[4], s = 0.f;
#pragma unroll
    for (int i = 0; i < 4; i++) { x[i] = hrow[tid + 256 * i]; s += x[i]; }
    if (tid < F_FEAT) sfeat[tid] = feat[(size_t)t * F_FEAT + tid];
    red[tid] = s;
    __syncthreads();
    for (int off = 128; off > 0; off >>= 1) {
        if (tid < off) red[tid] += red[tid + off];
        __syncthreads();
    }
    const float mu = red[0] * (1.0f / 1024.0f);
    __syncthreads();
    float v = 0.f;
#pragma unroll
    for (int i = 0; i < 4; i++) { float d = x[i] - mu; v += d * d; }
    red[tid] = v;
    __syncthreads();
    for (int off = 128; off > 0; off >>= 1) {
        if (tid < off) red[tid] += red[tid + off];
        __syncthreads();
    }
    const float rstd = rsqrtf(red[0] * (1.0f / 1024.0f) + 1e-5f);
#pragma unroll
    for (int i = 0; i < 4; i++) {
        int d = tid + 256 * i;
        float hv = (x[i] - mu) * rstd * ln_g[d] + ln_b[d];
        bf16 hi, lo; split_bf16(hv, hi, lo);
        g_ah[(size_t)t * D_HID + d] = hi;
        g_al[(size_t)t * D_HID + d] = lo;
    }
    if (tid < DFE) {
        float acc = stage_b[tid];
#pragma unroll
        for (int f = 0; f < F_FEAT; f++) acc += sfeat[f] * stage_W[f * DFE + tid];
        bf16 hi, lo; split_bf16(acc, hi, lo);
        g_sfe_h[(size_t)t * DFE + tid] = hi;
        g_sfe_l[(size_t)t * DFE + tid] = lo;
    }
    for (int idx = tid; idx < NB * DFE; idx += 256) {
        int g = idx >> 7, j = idx & 127;
        float acc = bproj_b[g * DFE + j];
#pragma unroll
        for (int f = 0; f < FPB; f++)
            acc += sfeat[g * FPB + f] * bproj_W[(g * FPB + f) * DFE + j];
        bf16 hi, lo; split_bf16(acc, hi, lo);
        g_bemb_h[(size_t)t * (NB * DFE) + idx] = hi;
        g_bemb_l[(size_t)t * (NB * DFE) + idx] = lo;
    }
}

// ---------------------------------------------------------------------------
// Transpose + bf16 split.
// W=1: ex_W1[z] (1024x512) -> w1t;  W=2: ex_W2 flat (8192x1024) -> w2t;
// W=3: br_W1 (1152x256) -> wbr;     W=4: ir_W1[z] (1152x256) -> wir.
// ---------------------------------------------------------------------------
template <int W>
__global__ void __launch_bounds__(256) transpose_split(const float* __restrict__ src)
{
    __shared__ float tl[32][33];
    const int z = blockIdx.z;
    const int C = (W == 1) ? DEH : ((W == 2) ? D_HID : DRH);
    const size_t dld = (W == 1) ? D_HID : ((W == 2) ? NEH : RIN);
    const size_t srcz = (W == 1) ? (size_t)D_HID * DEH : ((W == 4) ? (size_t)RIN * DRH : 0);
    const int dstz = (W == 1) ? DEH : ((W == 4) ? DRH : 0);
    const float* s = src + (size_t)z * srcz;
    const int r0 = blockIdx.y * 32, c0 = blockIdx.x * 32;
    const int tx = threadIdx.x & 31, ty = threadIdx.x >> 5;
#pragma unroll
    for (int i = 0; i < 4; i++)
        tl[ty + i * 8][tx] = s[(size_t)(r0 + ty + i * 8) * C + c0 + tx];
    __syncthreads();
#pragma unroll
    for (int i = 0; i < 4; i++) {
        int c = c0 + ty + i * 8;
        float v = tl[tx][ty + i * 8];
        size_t o = ((size_t)z * dstz + c) * dld + r0 + tx;
        bf16 hi, lo; split_bf16(v, hi, lo);
        if (W == 1)      { g_w1t_h[o] = hi; g_w1t_l[o] = lo; }
        else if (W == 2) { g_w2t_h[o] = hi; g_w2t_l[o] = lo; }
        else if (W == 3) { g_wbr_h[o] = hi; g_wbr_l[o] = lo; }
        else             { g_wir_h[o] = hi; g_wir_l[o] = lo; }
    }
}

// ---------------------------------------------------------------------------
// Gate kernel
// ---------------------------------------------------------------------------
__device__ __forceinline__ void top2sm4(const float* s, float* w) {
    float m1 = fmaxf(fmaxf(s[0], s[1]), fmaxf(s[2], s[3]));
    float m2 = -3.0e38f;
    bool used = false;
#pragma unroll
    for (int i = 0; i < 4; i++) {
        if (!used && s[i] == m1) used = true;
        else m2 = fmaxf(m2, s[i]);
    }
    float e[4], den = 0.f;
#pragma unroll
    for (int i = 0; i < 4; i++) {
        e[i] = (s[i] >= m2) ? expf(s[i] - m1) : 0.f;
        den += e[i];
    }
    float inv = 1.0f / den;
#pragma unroll
    for (int i = 0; i < 4; i++) w[i] = e[i] * inv;
}

__global__ void __launch_bounds__(128) gate_kernel(
    const float* __restrict__ br_W2, const float* __restrict__ br_b2,
    const float* __restrict__ ir_W2, const float* __restrict__ ir_b2,
    float* __restrict__ out)
{
    const int t = blockIdx.x, tid = threadIdx.x;
    __shared__ float sbh[DRH];
    __shared__ float sih[NB * DRH];
    __shared__ float slog[20];
    for (int i = tid; i < DRH; i += 128) sbh[i] = g_bh[(size_t)t * DRH + i];
    for (int i = tid; i < NB * DRH; i += 128) sih[i] = g_ih[(size_t)t * NB * DRH + i];
    __syncthreads();
    const int w = tid >> 5, lane = tid & 31;
    for (int d = w; d < 20; d += 4) {
        float s = 0.f;
        if (d < 4) {
            for (int k = lane; k < DRH; k += 32) s += sbh[k] * br_W2[k * NB + d];
        } else {
            int g = (d - 4) >> 2, e = (d - 4) & 3;
            const float* w2 = ir_W2 + g * DRH * ES;
            const float* ihg = sih + g * DRH;
            for (int k = lane; k < DRH; k += 32) s += ihg[k] * w2[k * ES + e];
        }
#pragma unroll
        for (int off = 16; off; off >>= 1) s += __shfl_xor_sync(0xffffffffu, s, off);
        if (lane == 0) slog[d] = s + ((d < 4) ? br_b2[d] : ir_b2[d - 4]);
    }
    __syncthreads();
    if (tid == 0) {
        float bl[4], bw[4], il[16], iw[16];
#pragma unroll
        for (int i = 0; i < 4; i++) bl[i] = slog[i];
#pragma unroll
        for (int i = 0; i < 16; i++) il[i] = slog[4 + i];
        top2sm4(bl, bw);
#pragma unroll
        for (int g = 0; g < 4; g++) top2sm4(&il[g * 4], &iw[g * 4]);
#pragma unroll
        for (int g = 0; g < 4; g++) {
            out[OFF_BW + (size_t)t * NB + g] = bw[g];
            out[OFF_BL + (size_t)t * NB + g] = bl[g];
#pragma unroll
            for (int e = 0; e < 4; e++) {
                int idx = g * 4 + e;
                float gw = bw[g] * iw[idx];
                out[OFF_GW + (size_t)t * NE + idx] = gw;
                out[OFF_GL + (size_t)t * NE + idx] = bl[g] + il[idx];
                g_gate[(size_t)t * NE + idx] = gw;
            }
        }
    }
}

// gbias[t,d] = sum_e gate[t,e] * ex_b2[e,d]
__global__ void __launch_bounds__(256) gbias_kernel(const float* __restrict__ ex_b2)
{
    const int t = blockIdx.x;
    __shared__ float sg[NE];
    if (threadIdx.x < NE) sg[threadIdx.x] = g_gate[(size_t)t * NE + threadIdx.x];
    __syncthreads();
    const int d = threadIdx.x * 4;
    float4 a = {0.f, 0.f, 0.f, 0.f};
#pragma unroll
    for (int e = 0; e < NE; e++) {
        float4 b = *(const float4*)&ex_b2[e * D_HID + d];
        a.x = fmaf(sg[e], b.x, a.x); a.y = fmaf(sg[e], b.y, a.y);
        a.z = fmaf(sg[e], b.z, a.z); a.w = fmaf(sg[e], b.w, a.w);
    }
    *(float4*)&g_gbias[(size_t)t * D_HID + d] = a;
}

// ---------------------------------------------------------------------------
// Shared HMMA machinery. CTA 128x128, K-chunk 32, 8 warps (warp 64x32),
// cp.async double-buffered, ldmatrix non-trans (A [m][k], B [n][k]).
// ---------------------------------------------------------------------------
#define LDT 40                        // padded row (32 + 8 bf16)
#define SAB (128 * LDT * 2)           // one matrix tile bytes = 10240
#define BUFB (4 * SAB)                // buffer bytes = 40960
#define DSM_MMA (2 * BUFB)            // 81920

__device__ __forceinline__ void load_ab(
    uint32_t sbase, const bf16* __restrict__ Ah, const bf16* __restrict__ Al, int lda,
    const bf16* __restrict__ Bh, const bf16* __restrict__ Bl, int ldb, int tid)
{
#pragma unroll
    for (int i = 0; i < 2; i++) {
        int q = i * 256 + tid;                 // 0..511
        int row = q >> 2, seg = q & 3;
        uint32_t so = (uint32_t)(row * LDT + seg * 8) * 2;
        cpa16(sbase + so,            Ah + (size_t)row * lda + seg * 8);
        cpa16(sbase + SAB + so,      Al + (size_t)row * lda + seg * 8);
        cpa16(sbase + 2 * SAB + so,  Bh + (size_t)row * ldb + seg * 8);
        cpa16(sbase + 3 * SAB + so,  Bl + (size_t)row * ldb + seg * 8);
    }
}

// 3-term MMA over one resident chunk buffer.
__device__ __forceinline__ void chunk_mma(
    float acc[4][4][4], uint32_t ab, int mw, int nw, int lane)
{
    const uint32_t bb = ab + 2 * SAB;
#pragma unroll
    for (int ks = 0; ks < 32; ks += 16) {
        uint32_t ah[4][4], al[4][4], bhf[2][4], blf[2][4];
#pragma unroll
        for (int mi = 0; mi < 4; mi++) {
            uint32_t ra = ab + (uint32_t)((mw + mi * 16 + (lane & 15)) * LDT
                                          + ks + ((lane >> 4) & 1) * 8) * 2;
            ldsm4(ah[mi], ra);
            ldsm4(al[mi], ra + SAB);
        }
#pragma unroll
        for (int pj = 0; pj < 2; pj++) {
            uint32_t rb = bb + (uint32_t)((nw + pj * 16 + ((lane >> 4) & 1) * 8
                                           + (lane & 7)) * LDT
                                          + ks + ((lane >> 3) & 1) * 8) * 2;
            ldsm4(bhf[pj], rb);
            ldsm4(blf[pj], rb + SAB);
        }
#pragma unroll
        for (int mi = 0; mi < 4; mi++)
#pragma unroll
            for (int nj = 0; nj < 4; nj++) {
                const int pj = nj >> 1, sb = (nj & 1) * 2;
                mma16816(acc[mi][nj], ah[mi], &bhf[pj][sb]);
                mma16816(acc[mi][nj], ah[mi], &blf[pj][sb]);
                mma16816(acc[mi][nj], al[mi], &bhf[pj][sb]);
            }
    }
}

// ---------------------------------------------------------------------------
// Expert GEMMs (unchanged semantics from R8).
// EPI=1: ex1 (gelu(.+b1)*gate -> eh hi/lo).  EPI=2: ex2 (combine -> out).
// ---------------------------------------------------------------------------
template <int EPI>
__global__ void __launch_bounds__(256) mma_kernel(
    const float* __restrict__ b1, const float* __restrict__ hidden,
    const float* __restrict__ alpha_p, float* __restrict__ out)
{
    extern __shared__ bf16 dsm[];
    const uint32_t sbase = smem_u32(dsm);
    const int tid = threadIdx.x;
    const int wid = tid >> 5, lane = tid & 31;
    const int m0 = blockIdx.y * 128;
    const int n0 = blockIdx.x * 128;

    const int ldk = (EPI == 1) ? D_HID : NEH;
    const bf16* Ah = ((EPI == 1) ? g_ah : g_ehh) + (size_t)m0 * ldk;
    const bf16* Al = ((EPI == 1) ? g_al : g_ehl) + (size_t)m0 * ldk;
    const bf16* Bh = ((EPI == 1) ? g_w1t_h : g_w2t_h) + (size_t)n0 * ldk;
    const bf16* Bl = ((EPI == 1) ? g_w1t_l : g_w2t_l) + (size_t)n0 * ldk;
    const int nchunk = ldk / 32;

    const int mw = (wid >> 2) * 64;
    const int nw = (wid & 3) * 32;

    float acc[4][4][4];
#pragma unroll
    for (int a = 0; a < 4; a++)
#pragma unroll
        for (int b = 0; b < 4; b++)
#pragma unroll
            for (int c = 0; c < 4; c++) acc[a][b][c] = 0.f;

    load_ab(sbase, Ah, Al, ldk, Bh, Bl, ldk, tid);
    CP_COMMIT();

    for (int ci = 0; ci < nchunk; ci++) {
        if (ci + 1 < nchunk) {
            load_ab(sbase + ((ci + 1) & 1) * BUFB,
                    Ah + (ci + 1) * 32, Al + (ci + 1) * 32, ldk,
                    Bh + (ci + 1) * 32, Bl + (ci + 1) * 32, ldk, tid);
            CP_COMMIT();
            CP_WAIT1();
        } else {
            CP_WAIT0();
        }
        __syncthreads();
        chunk_mma(acc, sbase + (ci & 1) * BUFB, mw, nw, lane);
        __syncthreads();
    }

    const int mfrag = mw + (lane >> 2);
    const int nfrag = nw + (lane & 3) * 2;

    if (EPI == 1) {
        const int e = n0 >> 9;
#pragma unroll
        for (int mi = 0; mi < 4; mi++) {
            const int r0 = m0 + mfrag + mi * 16;
            const float gv0 = g_gate[(size_t)r0 * NE + e];
            const float gv1 = g_gate[(size_t)(r0 + 8) * NE + e];
#pragma unroll
            for (int nj = 0; nj < 4; nj++) {
                const int ng = n0 + nfrag + nj * 8;
                const float* c = acc[mi][nj];
                float o0 = gelu_f(c[0] + b1[ng])     * gv0;
                float o1 = gelu_f(c[1] + b1[ng + 1]) * gv0;
                float o2 = gelu_f(c[2] + b1[ng])     * gv1;
                float o3 = gelu_f(c[3] + b1[ng + 1]) * gv1;
                bf16 h0, l0, h1, l1, h2, l2, h3, l3;
                split_bf16(o0, h0, l0); split_bf16(o1, h1, l1);
                split_bf16(o2, h2, l2); split_bf16(o3, h3, l3);
                *(__nv_bfloat162*)&g_ehh[(size_t)r0 * NEH + ng]       = __halves2bfloat162(h0, h1);
                *(__nv_bfloat162*)&g_ehl[(size_t)r0 * NEH + ng]       = __halves2bfloat162(l0, l1);
                *(__nv_bfloat162*)&g_ehh[(size_t)(r0 + 8) * NEH + ng] = __halves2bfloat162(h2, h3);
                *(__nv_bfloat162*)&g_ehl[(size_t)(r0 + 8) * NEH + ng] = __halves2bfloat162(l2, l3);
            }
        }
    } else {
        const float alpha = *alpha_p;
#pragma unroll
        for (int mi = 0; mi < 4; mi++) {
            const int r0 = m0 + mfrag + mi * 16;
#pragma unroll
            for (int nj = 0; nj < 4; nj++) {
                const int ng = n0 + nfrag + nj * 8;
                const float* c = acc[mi][nj];
#pragma unroll
                for (int h = 0; h < 2; h++) {
                    const int r = r0 + h * 8;
                    const size_t go = (size_t)r * D_HID + ng;
                    float2 gb = *(const float2*)&g_gbias[go];
                    float2 hv = *(const float2*)&hidden[go];
                    float2 sd, nh;
                    sd.x = c[h * 2]     + gb.x;
                    sd.y = c[h * 2 + 1] + gb.y;
                    nh.x = hv.x + alpha * sd.x;
                    nh.y = hv.y + alpha * sd.y;
                    *(float2*)&out[OFF_SD + go] = sd;
                    *(float2*)&out[OFF_NH + go] = nh;
                }
            }
        }
    }
}

// ---------------------------------------------------------------------------
// Router GEMM1 on HMMA.  Grid (2, 64, 5):
//   z=0: bundle router, A=[hnorm | sfe], B=br_W1^T, out=g_bh
//   z=1..4: intra router g=z-1, A=[hnorm | bemb_g], B=ir_W1^T[g], out=g_ih
// K = 1152 = 36 chunks; chunks 0..31 read hnorm splits, 32..35 extra splits.
// ---------------------------------------------------------------------------
__global__ void __launch_bounds__(256) router_mma(
    const float* __restrict__ br_b1, const float* __restrict__ ir_b1)
{
    extern __shared__ bf16 dsm[];
    const uint32_t sbase = smem_u32(dsm);
    const int tid = threadIdx.x;
    const int wid = tid >> 5, lane = tid & 31;
    const int m0 = blockIdx.y * 128;
    const int nt0 = blockIdx.x * 128;
    const int z = blockIdx.z;

    const bf16 *EAh, *EAl, *Bh, *Bl;
    const float* bias;
    float* ob;
    int lda2, out_ld, ocol;
    if (z == 0) {
        EAh = g_sfe_h; EAl = g_sfe_l; lda2 = DFE;
        Bh = g_wbr_h + (size_t)nt0 * RIN; Bl = g_wbr_l + (size_t)nt0 * RIN;
        bias = br_b1 + nt0;
        ob = g_bh; out_ld = DRH; ocol = nt0;
    } else {
        const int g = z - 1;
        EAh = g_bemb_h + g * DFE; EAl = g_bemb_l + g * DFE; lda2 = NB * DFE;
        Bh = g_wir_h + ((size_t)g * DRH + nt0) * RIN;
        Bl = g_wir_l + ((size_t)g * DRH + nt0) * RIN;
        bias = ir_b1 + g * DRH + nt0;
        ob = g_ih; out_ld = NB * DRH; ocol = g * DRH + nt0;
    }

    const int mw = (wid >> 2) * 64;
    const int nw = (wid & 3) * 32;
    const int nchunk = RIN / 32;  // 36

    float acc[4][4][4];
#pragma unroll
    for (int a = 0; a < 4; a++)
#pragma unroll
        for (int b = 0; b < 4; b++)
#pragma unroll
            for (int c = 0; c < 4; c++) acc[a][b][c] = 0.f;

    // chunk loader with A-region select (boundary 1024 is chunk-aligned)
    auto load_rt = [&](int ci) {
        const int k0 = ci * 32;
        const bf16 *Ah, *Al;
        int lda;
        if (k0 < D_HID) {
            Ah = g_ah + (size_t)m0 * D_HID + k0;
            Al = g_al + (size_t)m0 * D_HID + k0;
            lda = D_HID;
        } else {
            Ah = EAh + (size_t)m0 * lda2 + (k0 - D_HID);
            Al = EAl + (size_t)m0 * lda2 + (k0 - D_HID);
            lda = lda2;
        }
        load_ab(sbase + (ci & 1) * BUFB, Ah, Al, lda, Bh + k0, Bl + k0, RIN, tid);
    };

    load_rt(0);
    CP_COMMIT();
    for (int ci = 0; ci < nchunk; ci++) {
        if (ci + 1 < nchunk) {
            load_rt(ci + 1);
            CP_COMMIT();
            CP_WAIT1();
        } else {
            CP_WAIT0();
        }
        __syncthreads();
        chunk_mma(acc, sbase + (ci & 1) * BUFB, mw, nw, lane);
        __syncthreads();
    }

    const int mfrag = mw + (lane >> 2);
    const int nfrag = nw + (lane & 3) * 2;
#pragma unroll
    for (int mi = 0; mi < 4; mi++) {
        const int r0 = m0 + mfrag + mi * 16;
#pragma unroll
        for (int nj = 0; nj < 4; nj++) {
            const int nl = nfrag + nj * 8;       // 0..127 within tile
            const float* c = acc[mi][nj];
            float b0 = bias[nl], b1v = bias[nl + 1];
            float2 o0, o1;
            o0.x = gelu_f(c[0] + b0);
            o0.y = gelu_f(c[1] + b1v);
            o1.x = gelu_f(c[2] + b0);
            o1.y = gelu_f(c[3] + b1v);
            *(float2*)&ob[(size_t)r0 * out_ld + ocol + nl]       = o0;
            *(float2*)&ob[(size_t)(r0 + 8) * out_ld + ocol + nl] = o1;
        }
    }
}

// ---------------------------------------------------------------------------
extern "C" void kernel_launch(void* const* d_in, const int* in_sizes, int n_in,
                              void* d_out, int out_size)
{
    const float* hidden  = (const float*)d_in[0];
    const float* feat    = (const float*)d_in[1];
    const float* ln_g    = (const float*)d_in[2];
    const float* ln_b    = (const float*)d_in[3];
    const float* stage_W = (const float*)d_in[4];
    const float* stage_b = (const float*)d_in[5];
    const float* bproj_W = (const float*)d_in[6];
    const float* bproj_b = (const float*)d_in[7];
    const float* br_W1   = (const float*)d_in[8];
    const float* br_b1   = (const float*)d_in[9];
    const float* br_W2   = (const float*)d_in[10];
    const float* br_b2   = (const float*)d_in[11];
    const float* ir_W1   = (const float*)d_in[12];
    const float* ir_b1   = (const float*)d_in[13];
    const float* ir_W2   = (const float*)d_in[14];
    const float* ir_b2   = (const float*)d_in[15];
    const float* ex_W1   = (const float*)d_in[16];
    const float* ex_b1   = (const float*)d_in[17];
    const float* ex_W2   = (const float*)d_in[18];
    const float* ex_b2   = (const float*)d_in[19];
    const float* alpha   = (const float*)d_in[20];
    float* out = (float*)d_out;

    cudaFuncSetAttribute(mma_kernel<1>, cudaFuncAttributeMaxDynamicSharedMemorySize, DSM_MMA);
    cudaFuncSetAttribute(mma_kernel<2>, cudaFuncAttributeMaxDynamicSharedMemorySize, DSM_MMA);
    cudaFuncSetAttribute(router_mma, cudaFuncAttributeMaxDynamicSharedMemorySize, DSM_MMA);

    prep_kernel<<<M_TOK, 256>>>(hidden, feat, ln_g, ln_b,
                                stage_W, stage_b, bproj_W, bproj_b);
    {
        dim3 g(DEH / 32, D_HID / 32, NE);
        transpose_split<1><<<g, 256>>>(ex_W1);
    }
    {
        dim3 g(D_HID / 32, NEH / 32, 1);
        transpose_split<2><<<g, 256>>>(ex_W2);
    }
    {
        dim3 g(DRH / 32, RIN / 32, 1);
        transpose_split<3><<<g, 256>>>(br_W1);
    }
    {
        dim3 g(DRH / 32, RIN / 32, NB);
        transpose_split<4><<<g, 256>>>(ir_W1);
    }
    {
        dim3 g(DRH / 128, M_TOK / 128, 1 + NB);
        router_mma<<<g, 256, DSM_MMA>>>(br_b1, ir_b1);
    }
    gate_kernel<<<M_TOK, 128>>>(br_W2, br_b2, ir_W2, ir_b2, out);
    gbias_kernel<<<M_TOK, 256>>>(ex_b2);
    {
        dim3 g(NEH / 128, M_TOK / 128, 1);
        mma_kernel<1><<<g, 256, DSM_MMA>>>(ex_b1, hidden, alpha, out);
    }
    {
        dim3 g(D_HID / 128, M_TOK / 128, 1);
        mma_kernel<2><<<g, 256, DSM_MMA>>>(ex_b1, hidden, alpha, out);
    }
}